// round 1
// baseline (speedup 1.0000x reference)
#include <cuda_runtime.h>
#include <cstdint>

// Batched C[b,n,m] = sum_e A[b,n,e] * B[b,m,e]
// b=8, n=m=2048, e=1024, fp32. TF32 mma.sync path (RNA-converted inputs).

#define BM 128            // CTA tile rows (n dimension)
#define BN 128            // CTA tile cols (m dimension)
#define BK 32             // K tile (e dimension)
#define PAD 4
#define LDS_STRIDE (BK + PAD)   // 36 floats -> conflict-free fragment loads

__device__ __forceinline__ uint32_t f2tf32(float f) {
    uint32_t r;
    asm("cvt.rna.tf32.f32 %0, %1;" : "=r"(r) : "f"(f));
    return r;
}

__global__ __launch_bounds__(256, 2)
void bmm_tf32_kernel(const float* __restrict__ A, const float* __restrict__ B,
                     float* __restrict__ C, int N, int M, int E) {
    __shared__ uint32_t As[BM * LDS_STRIDE];
    __shared__ uint32_t Bs[BN * LDS_STRIDE];

    const int b    = blockIdx.z;
    const int by   = blockIdx.y;     // n-tile
    const int bx   = blockIdx.x;     // m-tile
    const int tid  = threadIdx.x;
    const int warp = tid >> 5;
    const int lane = tid & 31;
    const int wm   = warp & 3;       // warp row   (4 along m-of-output-tile)
    const int wn   = warp >> 2;      // warp col   (2 along n-of-output-tile)
    const int g    = lane >> 2;      // groupID
    const int t    = lane & 3;       // threadID_in_group

    const float* Ab = A + (size_t)b * N * E + (size_t)(by * BM) * E;
    const float* Bb = B + (size_t)b * M * E + (size_t)(bx * BN) * E;

    float acc[2][8][4];
    #pragma unroll
    for (int i = 0; i < 2; i++)
        #pragma unroll
        for (int j = 0; j < 8; j++)
            #pragma unroll
            for (int r = 0; r < 4; r++) acc[i][j][r] = 0.f;

    const int lr = tid >> 3;        // 0..31  (row within pass)
    const int lc = (tid & 7) * 4;   // 0,4,...,28 (float4 column)

    for (int kb = 0; kb < E; kb += BK) {
        // ---- global -> smem (with RNA tf32 conversion) ----
        #pragma unroll
        for (int p = 0; p < 4; p++) {
            int r = p * 32 + lr;
            float4 va = *(const float4*)(Ab + (size_t)r * E + kb + lc);
            float4 vb = *(const float4*)(Bb + (size_t)r * E + kb + lc);
            uint32_t* da = &As[r * LDS_STRIDE + lc];
            da[0] = f2tf32(va.x); da[1] = f2tf32(va.y);
            da[2] = f2tf32(va.z); da[3] = f2tf32(va.w);
            uint32_t* db = &Bs[r * LDS_STRIDE + lc];
            db[0] = f2tf32(vb.x); db[1] = f2tf32(vb.y);
            db[2] = f2tf32(vb.z); db[3] = f2tf32(vb.w);
        }
        __syncthreads();

        // ---- compute: 4 k-steps of k=8 ----
        #pragma unroll
        for (int ks = 0; ks < 4; ks++) {
            const int k0 = ks * 8;
            uint32_t af[2][4], bf[8][2];
            #pragma unroll
            for (int i = 0; i < 2; i++) {
                int row = wm * 32 + i * 16;
                af[i][0] = As[(row + g    ) * LDS_STRIDE + k0 + t    ];
                af[i][1] = As[(row + g + 8) * LDS_STRIDE + k0 + t    ];
                af[i][2] = As[(row + g    ) * LDS_STRIDE + k0 + t + 4];
                af[i][3] = As[(row + g + 8) * LDS_STRIDE + k0 + t + 4];
            }
            #pragma unroll
            for (int j = 0; j < 8; j++) {
                int col = wn * 64 + j * 8;
                bf[j][0] = Bs[(col + g) * LDS_STRIDE + k0 + t    ];
                bf[j][1] = Bs[(col + g) * LDS_STRIDE + k0 + t + 4];
            }
            #pragma unroll
            for (int i = 0; i < 2; i++) {
                #pragma unroll
                for (int j = 0; j < 8; j++) {
                    asm volatile(
                        "mma.sync.aligned.m16n8k8.row.col.f32.tf32.tf32.f32 "
                        "{%0,%1,%2,%3}, {%4,%5,%6,%7}, {%8,%9}, {%0,%1,%2,%3};\n"
                        : "+f"(acc[i][j][0]), "+f"(acc[i][j][1]),
                          "+f"(acc[i][j][2]), "+f"(acc[i][j][3])
                        : "r"(af[i][0]), "r"(af[i][1]), "r"(af[i][2]), "r"(af[i][3]),
                          "r"(bf[j][0]), "r"(bf[j][1]));
                }
            }
        }
        __syncthreads();
    }

    // ---- epilogue: fp32 stores, 32B-sector-aligned float2 per fragment row ----
    float* Cb = C + (size_t)b * N * M;
    #pragma unroll
    for (int i = 0; i < 2; i++) {
        #pragma unroll
        for (int j = 0; j < 8; j++) {
            int row = by * BM + wm * 32 + i * 16 + g;
            int col = bx * BN + wn * 64 + j * 8 + 2 * t;
            *(float2*)(Cb + (size_t)row * M + col) =
                make_float2(acc[i][j][0], acc[i][j][1]);
            *(float2*)(Cb + (size_t)(row + 8) * M + col) =
                make_float2(acc[i][j][2], acc[i][j][3]);
        }
    }
}

extern "C" void kernel_launch(void* const* d_in, const int* in_sizes, int n_in,
                              void* d_out, int out_size) {
    const float* mat0 = (const float*)d_in[0];   // [8, 2048, 1024]
    const float* mat1 = (const float*)d_in[1];   // [8, 2048, 1024]
    float* out = (float*)d_out;                  // [8, 2048, 2048]
    const int bsz = 8, N = 2048, M = 2048, E = 1024;
    dim3 grid(M / BN, N / BM, bsz);
    bmm_tf32_kernel<<<grid, 256>>>(mat0, mat1, out, N, M, E);
}

// round 3
// speedup vs baseline: 1.2320x; 1.2320x over previous
#include <cuda_runtime.h>
#include <cstdint>

// Batched C[b,n,m] = sum_e A[b,n,e] * B[b,m,e]
// b=8, n=m=2048, e=1024, fp32.
// mma.sync m16n8k8 tf32, 128x256 CTA tile, 64x64 warp tiles,
// 3-stage cp.async pipeline, consumer-side cvt.rna.tf32.

#define TM 128
#define TN 256
#define BK 32
#define NSTG 3
#define EDIM 1024
#define NDIM 2048
#define MDIM 2048
#define NB 8
#define NCHUNK (EDIM / BK)
#define A_BYTES (TM * BK * 4)           // 16384
#define B_BYTES (TN * BK * 4)           // 32768
#define STG (A_BYTES + B_BYTES)         // 49152
#define SMEM_BYTES (NSTG * STG)         // 147456

__device__ __forceinline__ uint32_t f2tf32(float f) {
    uint32_t r;
    asm("cvt.rna.tf32.f32 %0, %1;" : "=r"(r) : "f"(f));
    return r;
}
__device__ __forceinline__ float lds32(uint32_t a) {
    float v;
    asm volatile("ld.shared.b32 %0, [%1];" : "=f"(v) : "r"(a));
    return v;
}
__device__ __forceinline__ void cp16(uint32_t dst, const float* src) {
    asm volatile("cp.async.cg.shared.global [%0], [%1], 16;"
                 :: "r"(dst), "l"(src) : "memory");
}

// Per-thread: 4 A-lines + 8 B-lines of 16B per chunk.
// Swizzle: 16B-chunk column XOR (row & 7)  -> conflict-free fragment LDS.
__device__ __forceinline__ void issue_chunk(uint32_t sbase, const float* Ab,
                                            const float* Bb, int chunk,
                                            int lr, int lc) {
    uint32_t st = sbase + (chunk % NSTG) * STG;
    #pragma unroll
    for (int i = 0; i < 4; i++) {
        int row = lr + 32 * i;
        cp16(st + row * 128 + ((lc ^ (row & 7)) * 16),
             Ab + (size_t)row * EDIM + chunk * BK + lc * 4);
    }
    #pragma unroll
    for (int i = 0; i < 8; i++) {
        int row = lr + 32 * i;
        cp16(st + A_BYTES + row * 128 + ((lc ^ (row & 7)) * 16),
             Bb + (size_t)row * EDIM + chunk * BK + lc * 4);
    }
    asm volatile("cp.async.commit_group;" ::: "memory");
}

__global__ __launch_bounds__(256, 1)
void bmm_tf32_v2(const float* __restrict__ A, const float* __restrict__ B,
                 float* __restrict__ C) {
    extern __shared__ char smem[];
    uint32_t sbase;
    asm("{ .reg .u64 t; cvta.to.shared.u64 t, %1; cvt.u32.u64 %0, t; }"
        : "=r"(sbase) : "l"(smem));

    const int tid  = threadIdx.x;
    const int warp = tid >> 5;
    const int lane = tid & 31;
    const int wm   = warp & 1;        // 2 row blocks of 64
    const int wn   = warp >> 1;       // 4 col blocks of 64
    const int g    = lane >> 2;       // groupID 0..7
    const int t    = lane & 3;        // thread-in-group

    const int b = blockIdx.z, by = blockIdx.y, bx = blockIdx.x;
    const float* Ab = A + ((size_t)b * NDIM + (size_t)by * TM) * EDIM;
    const float* Bb = B + ((size_t)b * MDIM + (size_t)bx * TN) * EDIM;

    const int lr = tid >> 3;          // 0..31
    const int lc = tid & 7;           // 16B chunk 0..7

    float acc[4][8][4];
    #pragma unroll
    for (int i = 0; i < 4; i++)
        #pragma unroll
        for (int j = 0; j < 8; j++)
            #pragma unroll
            for (int r = 0; r < 4; r++) acc[i][j][r] = 0.f;

    issue_chunk(sbase, Ab, Bb, 0, lr, lc);
    issue_chunk(sbase, Ab, Bb, 1, lr, lc);

    for (int c = 0; c < NCHUNK; c++) {
        asm volatile("cp.async.wait_group 1;" ::: "memory");
        __syncthreads();
        if (c + 2 < NCHUNK)
            issue_chunk(sbase, Ab, Bb, c + 2, lr, lc);
        else
            asm volatile("cp.async.commit_group;" ::: "memory");

        uint32_t sa = sbase + (c % NSTG) * STG;
        uint32_t sb = sa + A_BYTES;

        #pragma unroll
        for (int ks = 0; ks < 4; ks++) {
            const uint32_t ch0 = ((2 * ks) ^ g) * 16 + t * 4;
            const uint32_t ch1 = ((2 * ks + 1) ^ g) * 16 + t * 4;
            uint32_t af[4][4], bf[8][2];
            #pragma unroll
            for (int i = 0; i < 4; i++) {
                uint32_t r0 = sa + (wm * 64 + i * 16 + g) * 128;
                uint32_t r8 = r0 + 8 * 128;
                af[i][0] = f2tf32(lds32(r0 + ch0));
                af[i][1] = f2tf32(lds32(r8 + ch0));
                af[i][2] = f2tf32(lds32(r0 + ch1));
                af[i][3] = f2tf32(lds32(r8 + ch1));
            }
            #pragma unroll
            for (int j = 0; j < 8; j++) {
                uint32_t rb = sb + (wn * 64 + j * 8 + g) * 128;
                bf[j][0] = f2tf32(lds32(rb + ch0));
                bf[j][1] = f2tf32(lds32(rb + ch1));
            }
            #pragma unroll
            for (int i = 0; i < 4; i++) {
                #pragma unroll
                for (int j = 0; j < 8; j++) {
                    asm volatile(
                        "mma.sync.aligned.m16n8k8.row.col.f32.tf32.tf32.f32 "
                        "{%0,%1,%2,%3}, {%4,%5,%6,%7}, {%8,%9}, {%0,%1,%2,%3};\n"
                        : "+f"(acc[i][j][0]), "+f"(acc[i][j][1]),
                          "+f"(acc[i][j][2]), "+f"(acc[i][j][3])
                        : "r"(af[i][0]), "r"(af[i][1]),
                          "r"(af[i][2]), "r"(af[i][3]),
                          "r"(bf[j][0]), "r"(bf[j][1]));
                }
            }
        }
    }

    // Epilogue: direct fp32 stores (DRAM was 6%; not a bottleneck).
    float* Cb = C + (size_t)b * NDIM * MDIM;
    #pragma unroll
    for (int i = 0; i < 4; i++) {
        int row = by * TM + wm * 64 + i * 16 + g;
        #pragma unroll
        for (int j = 0; j < 8; j++) {
            int col = bx * TN + wn * 64 + j * 8 + 2 * t;
            *(float2*)(Cb + (size_t)row * MDIM + col) =
                make_float2(acc[i][j][0], acc[i][j][1]);
            *(float2*)(Cb + (size_t)(row + 8) * MDIM + col) =
                make_float2(acc[i][j][2], acc[i][j][3]);
        }
    }
}

extern "C" void kernel_launch(void* const* d_in, const int* in_sizes, int n_in,
                              void* d_out, int out_size) {
    const float* mat0 = (const float*)d_in[0];   // [8, 2048, 1024]
    const float* mat1 = (const float*)d_in[1];   // [8, 2048, 1024]
    float* out = (float*)d_out;                  // [8, 2048, 2048]
    cudaFuncSetAttribute(bmm_tf32_v2,
                         cudaFuncAttributeMaxDynamicSharedMemorySize, SMEM_BYTES);
    dim3 grid(MDIM / TN, NDIM / TM, NB);         // (8, 16, 8)
    bmm_tf32_v2<<<grid, 256, SMEM_BYTES>>>(mat0, mat1, out);
}